// round 9
// baseline (speedup 1.0000x reference)
#include <cuda_runtime.h>
#include <cuda_fp16.h>
#include <stdint.h>

// StackedUnidirLSTMDecoder: B=64, L=4, H=1024, T=128
#define BB    64
#define LL    4
#define HH    1024
#define TT    128
#define GG    4096
#define NCTA  128
#define NTHR  544               // 16 consumer warps + 1 producer warp
#define NSTEP (TT * LL)         // 512
#define RING  6
#define CHUNK_BYTES 32768       // 16 kt x 4 mt x 512B
#define TOTAL_CHUNKS (NSTEP * 8)
#define DYN_SMEM (1024 + RING * CHUNK_BYTES)   // 197632 bytes

// ---------------------------------------------------------------------------
// Device-global scratch
// ---------------------------------------------------------------------------
// W in mma B-fragment order fp16: [L][NCTA][kt=128][np=2][lane=32][8 halfs]
__device__ __align__(1024) __half g_Wp[(size_t)LL * NCTA * 128 * 512];
// A fragment blocks, contiguous-chunk layout: per (p,l) 256KB region;
// block(ktAll 0..127, mt 0..3) at byte (ktAll*4 + mt)*512. ktAll<64 = X, >=64 = H.
__device__ __align__(1024) __half g_A[2 * LL * 131072];
__device__ float  g_bias[LL * GG];
__device__ unsigned g_bar_cnt, g_bar_gen;

// ---------------------------------------------------------------------------
// Prologue 1: pack W into fragment order (proven since R2)
// ---------------------------------------------------------------------------
__global__ void pack_weights(const float* __restrict__ Wih,
                             const float* __restrict__ Whh) {
    int tid = blockIdx.x * blockDim.x + threadIdx.x;
    if (tid >= LL * NCTA * 128 * 32) return;
    int lane = tid & 31;
    int kt   = (tid >> 5) & 127;
    int cta  = (tid >> 12) & 127;
    int l    = tid >> 19;
    int c8 = lane >> 2;
    int kq = (lane & 3) * 2;
    #pragma unroll
    for (int np = 0; np < 2; np++)
        #pragma unroll
        for (int ntl = 0; ntl < 2; ntl++) {
            int nt = np * 2 + ntl;
            int n  = nt * 1024 + cta * 8 + c8;
            __half v[4];
            #pragma unroll
            for (int e = 0; e < 4; e++) {
                int k = kt * 16 + kq + (e & 1) + 8 * (e >> 1);
                float w = (k < HH) ? Wih[((size_t)l * GG + n) * HH + k]
                                   : Whh[((size_t)l * GG + n) * HH + (k - HH)];
                v[e] = __float2half(w);
            }
            size_t off = ((((size_t)(l * NCTA + cta) * 128 + kt) * 2 + np) * 32
                          + lane) * 8 + ntl * 4;
            *(uint2*)&g_Wp[off] = *(uint2*)v;
        }
}

// ---------------------------------------------------------------------------
// Prologue 2: init A (chunked block layout) + biases
// ---------------------------------------------------------------------------
__global__ void init_state(const float* __restrict__ x,
                           const float* __restrict__ h0,
                           const float* __restrict__ b_ih,
                           const float* __restrict__ b_hh) {
    int i = blockIdx.x * blockDim.x + threadIdx.x;
    if (i < LL * GG) g_bias[i] = b_ih[i] + b_hh[i];
    if (i >= LL * BB * HH) return;
    int k = i & (HH - 1);
    int r = (i >> 10) & (BB - 1);
    int l = i >> 16;

    int mt    = r >> 4;
    int lane  = (r & 7) * 4 + ((k & 7) >> 1);
    int reg   = ((r & 15) >> 3) + 2 * ((k & 15) >> 3);
    int inblk = lane * 8 + reg * 2 + (k & 1);
    int ktq   = k >> 4;

    g_A[(size_t)l * 131072 + ((64 + ktq) * 4 + mt) * 256 + inblk] = __float2half(h0[i]);
    if (l == 0)
        g_A[(size_t)(ktq * 4 + mt) * 256 + inblk] = __float2half(x[r * HH + k]);
}

// ---------------------------------------------------------------------------
// mbarrier / bulk-copy helpers (all CTA-local; no clusters)
// ---------------------------------------------------------------------------
__device__ __forceinline__ void mbar_init(uint32_t a, uint32_t cnt) {
    asm volatile("mbarrier.init.shared.b64 [%0], %1;" :: "r"(a), "r"(cnt) : "memory");
}
__device__ __forceinline__ void mbar_expect_tx(uint32_t a, uint32_t bytes) {
    asm volatile("mbarrier.arrive.expect_tx.shared.b64 _, [%0], %1;"
                 :: "r"(a), "r"(bytes) : "memory");
}
__device__ __forceinline__ void mbar_arrive(uint32_t a) {
    asm volatile("mbarrier.arrive.shared.b64 _, [%0];" :: "r"(a) : "memory");
}
__device__ __forceinline__ void mbar_wait_acq(uint32_t a, uint32_t ph) {
    uint32_t done;
    do {
        asm volatile(
            "{\n\t.reg .pred p;\n\t"
            "mbarrier.try_wait.parity.acquire.cta.shared::cta.b64 p, [%1], %2, 0x989680;\n\t"
            "selp.b32 %0, 1, 0, p;\n\t}"
            : "=r"(done) : "r"(a), "r"(ph) : "memory");
    } while (!done);
}
__device__ __forceinline__ void mbar_wait_rlx(uint32_t a, uint32_t ph) {
    uint32_t done;
    do {
        asm volatile(
            "{\n\t.reg .pred p;\n\t"
            "mbarrier.try_wait.parity.relaxed.cta.shared::cta.b64 p, [%1], %2, 0x989680;\n\t"
            "selp.b32 %0, 1, 0, p;\n\t}"
            : "=r"(done) : "r"(a), "r"(ph) : "memory");
    } while (!done);
}
__device__ __forceinline__ void bulk_g2s(uint32_t dst, const void* src, uint32_t bar) {
    asm volatile(
        "cp.async.bulk.shared::cta.global.mbarrier::complete_tx::bytes "
        "[%0], [%1], %2, [%3];"
        :: "r"(dst), "l"(src), "r"((uint32_t)CHUNK_BYTES), "r"(bar) : "memory");
}

__device__ __forceinline__ void grid_sync() {
    __syncthreads();
    if (threadIdx.x == 0) {
        unsigned gen;
        asm volatile("ld.acquire.gpu.global.u32 %0, [%1];" : "=r"(gen) : "l"(&g_bar_gen));
        unsigned prev;
        asm volatile("atom.acq_rel.gpu.global.add.u32 %0, [%1], 1;"
                     : "=r"(prev) : "l"(&g_bar_cnt));
        if (prev == NCTA - 1) {
            asm volatile("st.relaxed.gpu.global.u32 [%0], %1;" :: "l"(&g_bar_cnt), "r"(0u));
            asm volatile("st.release.gpu.global.u32 [%0], %1;" :: "l"(&g_bar_gen), "r"(gen + 1u));
        } else {
            unsigned cur;
            do {
                asm volatile("ld.acquire.gpu.global.u32 %0, [%1];" : "=r"(cur) : "l"(&g_bar_gen));
            } while (cur == gen);
        }
    }
    __syncthreads();
}

__device__ __forceinline__ void mma16816(float* d,
                                         unsigned a0, unsigned a1, unsigned a2, unsigned a3,
                                         unsigned b0, unsigned b1) {
    asm volatile(
        "mma.sync.aligned.m16n8k16.row.col.f32.f16.f16.f32 "
        "{%0,%1,%2,%3},{%4,%5,%6,%7},{%8,%9},{%0,%1,%2,%3};\n"
        : "+f"(d[0]), "+f"(d[1]), "+f"(d[2]), "+f"(d[3])
        : "r"(a0), "r"(a1), "r"(a2), "r"(a3), "r"(b0), "r"(b1));
}
__device__ __forceinline__ float sigm(float v) { return 1.0f / (1.0f + __expf(-v)); }
__device__ __forceinline__ float tanh_fast(float v) {
    return 2.0f / (1.0f + __expf(-2.0f * v)) - 1.0f;
}

// chunk position q (0..7) within a step -> kt-group u (H chunks first)
__device__ __forceinline__ int pos_to_u(int q) { return (q < 4) ? (q + 4) : (q - 4); }

// Producer: issue the 32KB bulk copy for chunk idx (ring-gated, CTA-local)
__device__ __forceinline__ void produce(int idx, uint32_t sbase) {
    int slot = idx % RING;
    int wrap = idx / RING;
    if (idx >= RING) mbar_wait_rlx(sbase + 64 + slot * 8, (wrap - 1) & 1);
    mbar_expect_tx(sbase + slot * 8, CHUNK_BYTES);
    int step = idx >> 3, q = idx & 7;
    int u = pos_to_u(q);
    int l = step & 3, p = (step >> 2) & 1;
    const char* src = (const char*)g_A + ((size_t)(p * LL + l)) * 262144
                    + (size_t)u * CHUNK_BYTES;
    bulk_g2s(sbase + 1024 + slot * CHUNK_BYTES, src, sbase + slot * 8);
}

// ---------------------------------------------------------------------------
// Persistent LSTM, sequential 512-cell chain. A staged per-CTA through a
// 6x32KB SMEM ring via cp.async.bulk; producer warp prefetches next step's
// H-chunks (written 4 steps earlier) during the current step's tail/barrier.
// Consumer warp (ks,wm): m-tile wm, kt ≡ ks (mod 4) within each chunk.
// ks=1..3 deposit partials to SMEM; ks=0 combines + register-resident update.
// ---------------------------------------------------------------------------
__global__ void __launch_bounds__(NTHR, 1)
lstm_persistent(const float* __restrict__ c0,
                float* __restrict__ out) {
    extern __shared__ __align__(1024) char dsm[];
    uint32_t sbase;
    asm("{\n\t.reg .u64 t;\n\tcvta.to.shared.u64 t, %1;\n\tcvt.u32.u64 %0, t;\n\t}"
        : "=r"(sbase) : "l"(dsm));

    const int tid  = threadIdx.x;
    const int w    = tid >> 5;
    const int lane = tid & 31;
    const int cta  = blockIdx.x;
    const int ks = w >> 2;          // consumer warps only (w < 16)
    const int wm = w & 3;
    const int qrow = lane >> 2;
    const int tq   = lane & 3;

    __shared__ float s_part[3][4][16][32];   // [ks-1][wm][acc idx][lane]

    if (tid == 0) {
        #pragma unroll
        for (int s2 = 0; s2 < RING; s2++) {
            mbar_init(sbase + s2 * 8, 1);            // full: producer expect_tx
            mbar_init(sbase + 64 + s2 * 8, 16);      // empty: 16 consumer warps
        }
        asm volatile("fence.proxy.async;" ::: "memory");
    }
    __syncthreads();

    // consumer cell state (register-resident, fixed (r,j) per thread)
    float creg[LL][4];
    if (w < 16 && ks == 0) {
        #pragma unroll
        for (int l = 0; l < LL; l++)
            #pragma unroll
            for (int hh2 = 0; hh2 < 2; hh2++)
                #pragma unroll
                for (int u = 0; u < 2; u++) {
                    int r = wm * 16 + qrow + hh2 * 8;
                    int j = cta * 8 + tq * 2 + u;
                    creg[l][hh2 * 2 + u] = c0[((size_t)l * BB + r) * HH + j];
                }
    }

    // producer prologue: H-chunks 0..2 of step 0 (h0 data, ready)
    if (w == 16 && lane == 0) {
        produce(0, sbase);
        produce(1, sbase);
        produce(2, sbase);
    }

    for (int s = 0; s < NSTEP; s++) {
        const int l = s & 3;
        const int t = s >> 2;
        const int p = t & 1;

        float acc[4][4];

        if (w == 16) {
            // producer: positions 3..7 of step s (X of s is now visible),
            // then H-chunks 0..2 of step s+1 (written 4 steps ago).
            if (lane == 0) {
                asm volatile("fence.proxy.async;" ::: "memory");
                #pragma unroll 1
                for (int j = 0; j < 8; j++) {
                    int idx = s * 8 + 3 + j;
                    if (idx < TOTAL_CHUNKS) produce(idx, sbase);
                }
            }
        } else {
            #pragma unroll
            for (int a = 0; a < 4; a++)
                #pragma unroll
                for (int b = 0; b < 4; b++) acc[a][b] = 0.0f;

            const char* __restrict__ Wl =
                (const char*)g_Wp + (size_t)(l * NCTA + cta) * 131072;

            #pragma unroll 1
            for (int q = 0; q < 8; q++) {
                int idx  = s * 8 + q;
                int slot = idx % RING;
                int u    = pos_to_u(q);
                mbar_wait_acq(sbase + slot * 8, (idx / RING) & 1);
                uint32_t abase = sbase + 1024 + slot * CHUNK_BYTES;

                #pragma unroll
                for (int i = 0; i < 4; i++) {
                    int ktl = 4 * i + ks;
                    int kt  = 16 * u + ktl;
                    uint4 a4;
                    asm volatile("ld.shared.v4.u32 {%0,%1,%2,%3}, [%4];"
                                 : "=r"(a4.x), "=r"(a4.y), "=r"(a4.z), "=r"(a4.w)
                                 : "r"(abase + (uint32_t)((ktl * 4 + wm) * 512 + lane * 16)));
                    uint4 w01 = *(const uint4*)(Wl + (size_t)kt * 1024 + lane * 16);
                    uint4 w23 = *(const uint4*)(Wl + (size_t)kt * 1024 + 512 + lane * 16);
                    mma16816(acc[0], a4.x, a4.y, a4.z, a4.w, w01.x, w01.y);
                    mma16816(acc[1], a4.x, a4.y, a4.z, a4.w, w01.z, w01.w);
                    mma16816(acc[2], a4.x, a4.y, a4.z, a4.w, w23.x, w23.y);
                    mma16816(acc[3], a4.x, a4.y, a4.z, a4.w, w23.z, w23.w);
                }
                if (lane == 0) mbar_arrive(sbase + 64 + slot * 8);
            }
            if (ks != 0) {
                #pragma unroll
                for (int g = 0; g < 4; g++)
                    #pragma unroll
                    for (int ci = 0; ci < 4; ci++)
                        s_part[ks - 1][wm][g * 4 + ci][lane] = acc[g][ci];
            }
        }

        __syncthreads();

        if (w < 16 && ks == 0) {
            #pragma unroll
            for (int g = 0; g < 4; g++)
                #pragma unroll
                for (int ci = 0; ci < 4; ci++)
                    acc[g][ci] += s_part[0][wm][g * 4 + ci][lane]
                                + s_part[1][wm][g * 4 + ci][lane]
                                + s_part[2][wm][g * 4 + ci][lane];

            char* dstH = (char*)g_A + ((size_t)((p ^ 1) * LL + l)) * 262144;
            char* dstX = (char*)g_A + ((l < LL - 1)
                         ? ((size_t)(p * LL + l + 1)) * 262144
                         : ((size_t)((p ^ 1) * LL)) * 262144);   // y feedback
            int blkH = (64 + (cta >> 1)) * 4 + wm;
            int blkX = ((cta >> 1)) * 4 + wm;
            int lobytes = lane * 16 + (cta & 1) * 8;

            const float* __restrict__ bl = g_bias + l * GG;
            int j0 = cta * 8 + tq * 2;

            #pragma unroll
            for (int hh2 = 0; hh2 < 2; hh2++) {
                int r = wm * 16 + qrow + hh2 * 8;
                float hn2[2];
                #pragma unroll
                for (int u = 0; u < 2; u++) {
                    int j  = j0 + u;
                    int ci = hh2 * 2 + u;
                    float gi = acc[0][ci] + bl[j];
                    float gf = acc[1][ci] + bl[1024 + j];
                    float gg = acc[2][ci] + bl[2048 + j];
                    float go = acc[3][ci] + bl[3072 + j];
                    float ig = sigm(gi), fg = sigm(gf), og = sigm(go);
                    float gt = tanh_fast(gg);
                    float cn = fg * creg[l][ci] + ig * gt;
                    creg[l][ci] = cn;
                    hn2[u] = og * tanh_fast(cn);
                }
                unsigned hv = (unsigned)__half_as_ushort(__float2half(hn2[0]))
                            | ((unsigned)__half_as_ushort(__float2half(hn2[1])) << 16);
                *(unsigned*)(dstH + (size_t)blkH * 512 + lobytes + hh2 * 4) = hv;
                *(unsigned*)(dstX + (size_t)blkX * 512 + lobytes + hh2 * 4) = hv;
                if (l == LL - 1)
                    *(float2*)&out[((size_t)r * TT + t) * HH + j0] =
                        make_float2(hn2[0], hn2[1]);
            }
        }
        grid_sync();
    }
}

// ---------------------------------------------------------------------------
// kernel_launch: pack -> init -> persistent run (graph-capturable)
// inputs: x, h0, c0, W_ih, W_hh, b_ih, b_hh, seq_len
// ---------------------------------------------------------------------------
extern "C" void kernel_launch(void* const* d_in, const int* in_sizes, int n_in,
                              void* d_out, int out_size) {
    const float* x   = (const float*)d_in[0];
    const float* h0  = (const float*)d_in[1];
    const float* c0  = (const float*)d_in[2];
    const float* Wih = (const float*)d_in[3];
    const float* Whh = (const float*)d_in[4];
    const float* bih = (const float*)d_in[5];
    const float* bhh = (const float*)d_in[6];
    float* out = (float*)d_out;

    cudaFuncSetAttribute(lstm_persistent,
                         cudaFuncAttributeMaxDynamicSharedMemorySize, DYN_SMEM);

    pack_weights<<<(LL * NCTA * 128 * 32) / 256, 256>>>(Wih, Whh);
    init_state<<<(LL * BB * HH + 255) / 256, 256>>>(x, h0, bih, bhh);
    lstm_persistent<<<NCTA, NTHR, DYN_SMEM>>>(c0, out);
}

// round 11
// speedup vs baseline: 1.1203x; 1.1203x over previous
#include <cuda_runtime.h>
#include <cuda_fp16.h>
#include <stdint.h>

// StackedUnidirLSTMDecoder: B=64, L=4, H=1024, T=128
#define BB    64
#define LL    4
#define HH    1024
#define TT    128
#define GG    4096
#define NCTA  128
#define NTHR  512             // 16 warps: (ks 0..3) x (wm 0..3)
#define NSTEP (TT * LL)       // 512

// ---------------------------------------------------------------------------
// Device-global scratch
// ---------------------------------------------------------------------------
// W in mma B-fragment order fp16: [L][NCTA][kt=128][np=2][lane=32][8 halfs]
__device__ __align__(1024) __half g_Wp[(size_t)LL * NCTA * 128 * 512];
// A fragment blocks (R5 layout): g_A[p][l][mt=4][ktAll=128][512B];
// ktAll 0..63 = X (layer input), 64..127 = H (recurrent)
__device__ __align__(1024) __half g_A[2][LL][4 * 128 * 256];
__device__ float  g_bias[LL * GG];
__device__ unsigned g_bar_cnt, g_bar_gen;

// ---------------------------------------------------------------------------
// Grid barrier (proven since R4)
// ---------------------------------------------------------------------------
__device__ __forceinline__ void grid_sync() {
    __syncthreads();
    if (threadIdx.x == 0) {
        unsigned gen;
        asm volatile("ld.acquire.gpu.global.u32 %0, [%1];" : "=r"(gen) : "l"(&g_bar_gen));
        unsigned prev;
        asm volatile("atom.acq_rel.gpu.global.add.u32 %0, [%1], 1;"
                     : "=r"(prev) : "l"(&g_bar_cnt));
        if (prev == NCTA - 1) {
            asm volatile("st.relaxed.gpu.global.u32 [%0], %1;" :: "l"(&g_bar_cnt), "r"(0u));
            asm volatile("st.release.gpu.global.u32 [%0], %1;" :: "l"(&g_bar_gen), "r"(gen + 1u));
        } else {
            unsigned cur;
            do {
                asm volatile("ld.acquire.gpu.global.u32 %0, [%1];" : "=r"(cur) : "l"(&g_bar_gen));
            } while (cur == gen);
        }
    }
    __syncthreads();
}

__device__ __forceinline__ void mma16816(float* d,
                                         unsigned a0, unsigned a1, unsigned a2, unsigned a3,
                                         unsigned b0, unsigned b1) {
    asm volatile(
        "mma.sync.aligned.m16n8k16.row.col.f32.f16.f16.f32 "
        "{%0,%1,%2,%3},{%4,%5,%6,%7},{%8,%9},{%0,%1,%2,%3};\n"
        : "+f"(d[0]), "+f"(d[1]), "+f"(d[2]), "+f"(d[3])
        : "r"(a0), "r"(a1), "r"(a2), "r"(a3), "r"(b0), "r"(b1));
}
__device__ __forceinline__ float sigm(float v) { return 1.0f / (1.0f + __expf(-v)); }
__device__ __forceinline__ float tanh_fast(float v) {
    return 2.0f / (1.0f + __expf(-2.0f * v)) - 1.0f;
}

// ---------------------------------------------------------------------------
// Single persistent kernel: phase0 pack W, phase1 init A/bias, phase2 run.
// CTA c owns gate cols {g*1024+j : j in [8c,8c+8)}.
// GEMM: warp (ks,wm) = m-tile wm, k-tiles [32ks,32ks+32), all via LDG.128.
// Reduce + cell update fully distributed: each thread finalizes ONE cell.
// ---------------------------------------------------------------------------
__global__ void __launch_bounds__(NTHR, 1)
lstm_main(const float* __restrict__ x,
          const float* __restrict__ h0,
          const float* __restrict__ c0,
          const float* __restrict__ Wih,
          const float* __restrict__ Whh,
          const float* __restrict__ b_ih,
          const float* __restrict__ b_hh,
          float* __restrict__ out) {
    const int cta  = blockIdx.x;
    const int tid  = threadIdx.x;
    const int w    = tid >> 5;
    const int lane = tid & 31;
    const int ks   = w >> 2;
    const int wm   = w & 3;

    __shared__ float s_part[4][4][16][32];   // [ks][wm][g*4+ci][lane]

    // ---------------- phase 0: pack W into fragment order -------------------
    for (int v = cta * NTHR + tid; v < LL * NCTA * 128 * 32; v += NCTA * NTHR) {
        int plane = v & 31;
        int pkt   = (v >> 5) & 127;
        int pcta  = (v >> 12) & 127;
        int pl    = v >> 19;
        int c8 = plane >> 2;
        int kq = (plane & 3) * 2;
        #pragma unroll
        for (int np = 0; np < 2; np++)
            #pragma unroll
            for (int ntl = 0; ntl < 2; ntl++) {
                int nt = np * 2 + ntl;
                int n  = nt * 1024 + pcta * 8 + c8;
                __half vv[4];
                #pragma unroll
                for (int e = 0; e < 4; e++) {
                    int k = pkt * 16 + kq + (e & 1) + 8 * (e >> 1);
                    float wv = (k < HH) ? Wih[((size_t)pl * GG + n) * HH + k]
                                        : Whh[((size_t)pl * GG + n) * HH + (k - HH)];
                    vv[e] = __float2half(wv);
                }
                size_t off = ((((size_t)(pl * NCTA + pcta) * 128 + pkt) * 2 + np) * 32
                              + plane) * 8 + ntl * 4;
                *(uint2*)&g_Wp[off] = *(uint2*)vv;
            }
    }

    // ---------------- phase 1: init A (x, h0) + biases ----------------------
    for (int v = cta * NTHR + tid; v < LL * BB * HH; v += NCTA * NTHR) {
        if (v < LL * GG) g_bias[v] = b_ih[v] + b_hh[v];
        int k = v & (HH - 1);
        int r = (v >> 10) & (BB - 1);
        int l = v >> 16;
        int mt    = r >> 4;
        int lane2 = (r & 7) * 4 + ((k & 7) >> 1);
        int reg   = ((r & 15) >> 3) + 2 * ((k & 15) >> 3);
        int inblk = lane2 * 8 + reg * 2 + (k & 1);
        g_A[0][l][(mt * 128 + 64 + (k >> 4)) * 256 + inblk] = __float2half(h0[v]);
        if (l == 0)
            g_A[0][0][(mt * 128 + (k >> 4)) * 256 + inblk] = __float2half(x[r * HH + k]);
    }
    grid_sync();

    // ---------------- per-thread cell ownership -----------------------------
    // thread (ks, wm, lane) owns cell (r_own, j_own):
    const int qrow2 = lane >> 1;                  // 0..15
    const int jj    = (lane & 1) * 4 + ks;        // 0..7
    const int qrowp = qrow2 & 7;
    const int hh2   = qrow2 >> 3;
    const int tqp   = jj >> 1;
    const int u     = jj & 1;
    const int lanep = qrowp * 4 + tqp;
    const int di    = hh2 * 2 + u;
    const int r_own = wm * 16 + qrow2;
    const int j_own = cta * 8 + jj;

    float bias[LL][4], creg[LL];
    #pragma unroll
    for (int l = 0; l < LL; l++) {
        #pragma unroll
        for (int g = 0; g < 4; g++)
            bias[l][g] = g_bias[l * GG + g * 1024 + j_own];
        creg[l] = c0[((size_t)l * BB + r_own) * HH + j_own];
    }

    const char* __restrict__ Wcta = (const char*)g_Wp + (size_t)cta * 131072;
    const int aoff = (wm * 128 + ks * 32) * 512 + lane * 16;
    const int woff = (ks * 32) * 1024 + lane * 16;
    const int inblk_own = lanep * 16 + (cta & 1) * 8 + hh2 * 4 + u * 2;

    // ---------------- phase 2: 512 sequential cell-steps --------------------
    for (int s = 0; s < NSTEP; s++) {
        const int l = s & 3;
        const int t = s >> 2;
        const int p = t & 1;

        const char* Ab = (const char*)&g_A[p][l][0] + aoff;
        const char* Wb = Wcta + (size_t)l * NCTA * 131072 + woff;

        float acc[4][4];
        #pragma unroll
        for (int a = 0; a < 4; a++)
            #pragma unroll
            for (int b = 0; b < 4; b++) acc[a][b] = 0.0f;

        #pragma unroll 4
        for (int kk = 0; kk < 32; kk++) {
            uint4 a   = __ldcg((const uint4*)(Ab + (size_t)kk * 512));
            uint4 w01 = *(const uint4*)(Wb + (size_t)kk * 1024);
            uint4 w23 = *(const uint4*)(Wb + (size_t)kk * 1024 + 512);
            mma16816(acc[0], a.x, a.y, a.z, a.w, w01.x, w01.y);
            mma16816(acc[1], a.x, a.y, a.z, a.w, w01.z, w01.w);
            mma16816(acc[2], a.x, a.y, a.z, a.w, w23.x, w23.y);
            mma16816(acc[3], a.x, a.y, a.z, a.w, w23.z, w23.w);
        }

        // all 16 warps deposit partials
        #pragma unroll
        for (int g = 0; g < 4; g++)
            #pragma unroll
            for (int ci = 0; ci < 4; ci++)
                s_part[ks][wm][g * 4 + ci][lane] = acc[g][ci];
        __syncthreads();

        // distributed reduce + cell update: each thread finalizes ONE cell
        float gate[4];
        #pragma unroll
        for (int g = 0; g < 4; g++)
            gate[g] = s_part[0][wm][g * 4 + di][lanep]
                    + s_part[1][wm][g * 4 + di][lanep]
                    + s_part[2][wm][g * 4 + di][lanep]
                    + s_part[3][wm][g * 4 + di][lanep];

        float gi = gate[0] + bias[l][0];
        float gf = gate[1] + bias[l][1];
        float gg = gate[2] + bias[l][2];
        float go = gate[3] + bias[l][3];
        float ig = sigm(gi), fg = sigm(gf), og = sigm(go);
        float gt = tanh_fast(gg);
        float cn = fg * creg[l] + ig * gt;
        creg[l] = cn;
        float hn = og * tanh_fast(cn);
        __half hv = __float2half(hn);

        char* dstH = (char*)&g_A[p ^ 1][l][0];
        char* dstX = (l < LL - 1) ? (char*)&g_A[p][l + 1][0]
                                  : (char*)&g_A[p ^ 1][0][0];   // y feedback
        *(__half*)(dstH + (size_t)(wm * 128 + 64 + (cta >> 1)) * 512 + inblk_own) = hv;
        *(__half*)(dstX + (size_t)(wm * 128 + (cta >> 1)) * 512 + inblk_own) = hv;
        if (l == LL - 1)
            out[((size_t)r_own * TT + t) * HH + j_own] = hn;

        grid_sync();
    }
}

// ---------------------------------------------------------------------------
// kernel_launch: ONE persistent kernel (graph has a single node)
// inputs: x, h0, c0, W_ih, W_hh, b_ih, b_hh, seq_len
// ---------------------------------------------------------------------------
extern "C" void kernel_launch(void* const* d_in, const int* in_sizes, int n_in,
                              void* d_out, int out_size) {
    const float* x   = (const float*)d_in[0];
    const float* h0  = (const float*)d_in[1];
    const float* c0  = (const float*)d_in[2];
    const float* Wih = (const float*)d_in[3];
    const float* Whh = (const float*)d_in[4];
    const float* bih = (const float*)d_in[5];
    const float* bhh = (const float*)d_in[6];
    float* out = (float*)d_out;

    lstm_main<<<NCTA, NTHR>>>(x, h0, c0, Wih, Whh, bih, bhh, out);
}